// round 12
// baseline (speedup 1.0000x reference)
#include <cuda_runtime.h>
#include <cuda_bf16.h>
#include <cstdint>

#define DIM     64
#define KC      8192
#define NP      32768
#define MT      64           // points per CTA
#define NT      64           // codes per tile
#define NTILES  (KC / NT)    // 128
#define GT      256
#define SMLD    400          // row stride bytes (25*16, odd -> conflict-free ldsm)

// A: [point][200 bf16] (cols 192..199 zero pad)
__device__ __align__(16) __nv_bfloat16 d_A2[NP * 200];   // 13.1 MB
// B: [code][200 bf16]
__device__ __align__(16) __nv_bfloat16 d_B2[KC * 200];   // 3.3 MB
__device__ __align__(16) float d_cn[KC];
__device__ int2  d_cand[NP];

// SMEM: A 64x400 | B 2x 64x400 | cn 2x 256B | mbar 2x8
#define S_A    0
#define S_B    25600
#define BUFSZ  25600
#define S_CN   76800
#define S_MB   77312
#define SMEM_G 77344

// ---------------------------------------------------------------------------
// helpers (all generic PTX, sm_90)
// ---------------------------------------------------------------------------
__device__ __forceinline__ uint32_t smem_u32(const void* p) {
    uint32_t a;
    asm("{ .reg .u64 t; cvta.to.shared.u64 t, %1; cvt.u32.u64 %0, t; }"
        : "=r"(a) : "l"(p));
    return a;
}
__device__ __forceinline__ void bulkcp(uint32_t dst, const void* src,
                                       uint32_t bytes, uint32_t mbar) {
    asm volatile(
        "cp.async.bulk.shared::cluster.global.mbarrier::complete_tx::bytes "
        "[%0], [%1], %2, [%3];"
        :: "r"(dst), "l"(src), "r"(bytes), "r"(mbar) : "memory");
}
#define MBAR_INIT(a, n) \
    asm volatile("mbarrier.init.shared.b64 [%0], %1;" :: "r"(a), "r"(n) : "memory")
#define MBAR_EXPECT(a, bytes) \
    asm volatile("mbarrier.arrive.expect_tx.shared.b64 _, [%0], %1;" \
                 :: "r"(a), "r"(bytes) : "memory")
__device__ __forceinline__ void mbar_wait(uint32_t mbar, uint32_t parity) {
    asm volatile(
        "{\n\t.reg .pred P;\n\t"
        "WL_%=:\n\t"
        "mbarrier.try_wait.parity.acquire.cta.shared::cta.b64 P, [%0], %1, 0x989680;\n\t"
        "@P bra.uni WD_%=;\n\t"
        "bra.uni WL_%=;\n\t"
        "WD_%=:\n\t}"
        :: "r"(mbar), "r"(parity) : "memory");
}
__device__ __forceinline__ void ldm_x4(uint32_t* r, uint32_t addr) {
    asm volatile("ldmatrix.sync.aligned.m8n8.x4.shared.b16 {%0,%1,%2,%3}, [%4];"
                 : "=r"(r[0]), "=r"(r[1]), "=r"(r[2]), "=r"(r[3]) : "r"(addr));
}
__device__ __forceinline__ void mma_bf16(float* d, const uint32_t* a,
                                         uint32_t b0, uint32_t b1) {
    asm volatile(
        "mma.sync.aligned.m16n8k16.row.col.f32.bf16.bf16.f32 "
        "{%0,%1,%2,%3}, {%4,%5,%6,%7}, {%8,%9}, {%0,%1,%2,%3};"
        : "+f"(d[0]), "+f"(d[1]), "+f"(d[2]), "+f"(d[3])
        : "r"(a[0]), "r"(a[1]), "r"(a[2]), "r"(a[3]), "r"(b0), "r"(b1));
}

// ---------------------------------------------------------------------------
// prep kernels
// ---------------------------------------------------------------------------
__global__ void __launch_bounds__(256) prep_cn(const float* __restrict__ cb) {
    int k = blockIdx.x * 256 + threadIdx.x;
    const float* row = cb + (size_t)k * DIM;
    float s = 0.f;
#pragma unroll
    for (int i = 0; i < DIM; i++)
        s = __fadd_rn(s, __fmul_rn(row[i], row[i]));
    d_cn[k] = s;
}

// A' rows: [hi(64) | lo(64) | hi(64) | pad(8)]
__global__ void __launch_bounds__(256) prep_A(const float* __restrict__ ze) {
    __shared__ float xs[DIM * 128];
    const int tid = threadIdx.x;
    const int n0  = blockIdx.x * 128;
    const int b   = n0 >> 12;
    const int hw0 = n0 & 4095;
    const float* zb = ze + (size_t)b * DIM * 4096 + hw0;
#pragma unroll
    for (int it = 0; it < 32; it++) {
        int e = tid + it * 256;
        int nl = e & 127, d = e >> 7;
        xs[d * 128 + nl] = zb[(size_t)d * 4096 + nl];
    }
    __syncthreads();
    uint32_t* out = (uint32_t*)d_A2 + (size_t)blockIdx.x * 12800;
#pragma unroll
    for (int i = 0; i < 50; i++) {
        int e   = tid + i * 256;      // 0..12799
        int row = e / 100;
        int c   = e % 100;            // uint col (2 bf16)
        uint32_t u = 0u;
        if (c < 96) {
            int blk = c >> 5;         // 0:hi 1:lo 2:hi
            int d0  = (c & 31) * 2;
            float v0 = xs[d0 * 128 + row], v1 = xs[(d0 + 1) * 128 + row];
            __nv_bfloat16 h0 = __float2bfloat16(v0);
            __nv_bfloat16 h1 = __float2bfloat16(v1);
            if (blk == 1) {
                h0 = __float2bfloat16(v0 - __bfloat162float(h0));
                h1 = __float2bfloat16(v1 - __bfloat162float(h1));
            }
            u = (uint32_t)__bfloat16_as_ushort(h0) |
                ((uint32_t)__bfloat16_as_ushort(h1) << 16);
        }
        out[row * 100 + c] = u;
    }
}

// B' rows: [hi | hi | lo | pad(8)]
__global__ void __launch_bounds__(256) prep_B(const float* __restrict__ cb) {
    int idx = blockIdx.x * 256 + threadIdx.x;   // 0 .. 8192*100-1
    int row = idx / 100;
    int c   = idx % 100;
    uint32_t u = 0u;
    if (c < 96) {
        int blk = c >> 5;             // 0:hi 1:hi 2:lo
        int d0  = (c & 31) * 2;
        float v0 = cb[(size_t)row * 64 + d0], v1 = cb[(size_t)row * 64 + d0 + 1];
        __nv_bfloat16 h0 = __float2bfloat16(v0);
        __nv_bfloat16 h1 = __float2bfloat16(v1);
        if (blk == 2) {
            h0 = __float2bfloat16(v0 - __bfloat162float(h0));
            h1 = __float2bfloat16(v1 - __bfloat162float(h1));
        }
        u = (uint32_t)__bfloat16_as_ushort(h0) |
            ((uint32_t)__bfloat16_as_ushort(h1) << 16);
    }
    ((uint32_t*)d_B2)[(size_t)row * 100 + c] = u;
}

// ---------------------------------------------------------------------------
// GEMM (mma.sync bf16), MT=64, warp tile 16x32, 3 CTAs/SM target
// ---------------------------------------------------------------------------
__global__ void __launch_bounds__(GT, 3) gemm_kernel() {
    extern __shared__ char smem[];
    const uint32_t sb = smem_u32(smem);
    const int tid = threadIdx.x;
    const int wid = tid >> 5;
    const int l   = tid & 31;
    const int wm  = wid & 3;          // M-warp 0..3 (16 rows each)
    const int wn  = wid >> 2;         // N-warp 0..1 (32 cols each)
    const int m0  = blockIdx.x * MT;

    if (tid == 0) {
        MBAR_INIT(sb + S_MB, 1);
        MBAR_INIT(sb + S_MB + 8, 1);
    }
    __syncthreads();
    if (tid == 0) {
        // stage 0: A + B0 + cn0
        MBAR_EXPECT(sb + S_MB, 25600u + 25600u + 256u);
        bulkcp(sb + S_A, (const char*)d_A2 + (size_t)blockIdx.x * 25600, 25600u,
               sb + S_MB);
        bulkcp(sb + S_B, (const char*)d_B2, 25600u, sb + S_MB);
        bulkcp(sb + S_CN, (const char*)d_cn, 256u, sb + S_MB);
        // stage 1: B1 + cn1
        MBAR_EXPECT(sb + S_MB + 8, 25856u);
        bulkcp(sb + S_B + BUFSZ, (const char*)d_B2 + 25600, 25600u, sb + S_MB + 8);
        bulkcp(sb + S_CN + 256, (const char*)d_cn + 256, 256u, sb + S_MB + 8);
    }

    // ldmatrix per-thread base addresses
    const uint32_t aA = sb + S_A + (wm * 16 + (l & 15)) * SMLD + (l >> 4) * 16;
    const uint32_t bRow = (uint32_t)(wn * 32 + (l & 7) + ((l >> 3) & 1) * 8);
    const uint32_t aB0 = sb + S_B + bRow * SMLD + (l >> 4) * 16;
    const uint32_t aB1 = aB0 + 16 * SMLD;

    const int cb0 = wn * 32 + 2 * (l & 3);   // epilogue column base

    // 4 trackers: s = row_half*2 + (j&1)
    float b1[4], b2[4];
    int   i1[4], i2[4];
#pragma unroll
    for (int s = 0; s < 4; s++) { b1[s] = 3.4e38f; b2[s] = 3.4e38f; i1[s] = 0; i2[s] = 0; }

#pragma unroll 1
    for (int t = 0; t < NTILES; t++) {
        const int buf = t & 1;
        const uint32_t boff = (uint32_t)buf * BUFSZ;
        mbar_wait(sb + S_MB + 8 * buf, (t >> 1) & 1);

        float acc[4][4];
#pragma unroll
        for (int j = 0; j < 4; j++)
#pragma unroll
            for (int q = 0; q < 4; q++) acc[j][q] = 0.f;

#pragma unroll
        for (int ks = 0; ks < 12; ks++) {
            const uint32_t koff = (uint32_t)(ks * 32);   // 16 bf16 = 32 B
            uint32_t ra[4], rb01[4], rb23[4];
            ldm_x4(ra,   aA + koff);
            ldm_x4(rb01, aB0 + boff + koff);
            ldm_x4(rb23, aB1 + boff + koff);
            mma_bf16(acc[0], ra, rb01[0], rb01[2]);
            mma_bf16(acc[1], ra, rb01[1], rb01[3]);
            mma_bf16(acc[2], ra, rb23[0], rb23[2]);
            mma_bf16(acc[3], ra, rb23[1], rb23[3]);
        }

        // hoist cn slice into regs (buffer overwritten by t+2 copy)
        const float* cnp = (const float*)(smem + S_CN + buf * 256);
        float creg[8];
#pragma unroll
        for (int j = 0; j < 4; j++) {
            creg[2 * j]     = cnp[cb0 + j * 8];
            creg[2 * j + 1] = cnp[cb0 + j * 8 + 1];
        }

        __syncthreads();                       // all warps done with buf
        if (tid == 0 && t + 2 < NTILES) {
            uint32_t mb = sb + S_MB + 8 * buf;
            MBAR_EXPECT(mb, 25856u);
            bulkcp(sb + S_B + boff, (const char*)d_B2 + (size_t)(t + 2) * 25600,
                   25600u, mb);
            bulkcp(sb + S_CN + buf * 256, (const char*)d_cn + (size_t)(t + 2) * 256,
                   256u, mb);
        }

        // epilogue: score = nc - 2*m; 4 independent top-2 chains (depth 4)
        const int kb0 = t * NT + cb0;
#pragma unroll
        for (int j = 0; j < 4; j++) {
            float c0 = creg[2 * j];
            float c1 = creg[2 * j + 1];
            int kk = kb0 + j * 8;
            const int par = j & 1;
            const int s0 = par;            // row (l>>2)
            const int s1 = 2 + par;        // row (l>>2)+8
            float v0 = fmaf(-2.f, acc[j][0], c0);
            float v1 = fmaf(-2.f, acc[j][1], c1);
            float v2 = fmaf(-2.f, acc[j][2], c0);
            float v3 = fmaf(-2.f, acc[j][3], c1);
            if (v0 < b1[s0]) { b2[s0] = b1[s0]; i2[s0] = i1[s0]; b1[s0] = v0; i1[s0] = kk; }
            else if (v0 < b2[s0]) { b2[s0] = v0; i2[s0] = kk; }
            if (v1 < b1[s0]) { b2[s0] = b1[s0]; i2[s0] = i1[s0]; b1[s0] = v1; i1[s0] = kk + 1; }
            else if (v1 < b2[s0]) { b2[s0] = v1; i2[s0] = kk + 1; }
            if (v2 < b1[s1]) { b2[s1] = b1[s1]; i2[s1] = i1[s1]; b1[s1] = v2; i1[s1] = kk; }
            else if (v2 < b2[s1]) { b2[s1] = v2; i2[s1] = kk; }
            if (v3 < b1[s1]) { b2[s1] = b1[s1]; i2[s1] = i1[s1]; b1[s1] = v3; i1[s1] = kk + 1; }
            else if (v3 < b2[s1]) { b2[s1] = v3; i2[s1] = kk + 1; }
        }
    }

    // merge parity trackers -> 2 row slots (row halves)
    float m1[2], m2[2];
    int   n1[2], n2i[2];
#pragma unroll
    for (int h = 0; h < 2; h++) {
        float a1 = b1[2 * h], a2 = b2[2 * h];
        int   x1 = i1[2 * h], x2 = i2[2 * h];
        float c1v = b1[2 * h + 1], c2v = b2[2 * h + 1];
        int   y1 = i1[2 * h + 1], y2 = i2[2 * h + 1];
        if (c1v < a1) {
            float t2v = fminf(a1, c2v);
            int   t2i = (c2v < a1) ? y2 : x1;
            a2 = t2v; x2 = t2i;
            a1 = c1v; x1 = y1;
        } else if (c1v < a2) {
            a2 = c1v; x2 = y1;
        }
        m1[h] = a1; n1[h] = x1; m2[h] = a2; n2i[h] = x2;
    }

    // quad merge (lanes sharing l>>2 hold same rows)
#pragma unroll
    for (int h = 0; h < 2; h++) {
#pragma unroll
        for (int off = 1; off <= 2; off <<= 1) {
            float t1 = __shfl_xor_sync(0xFFFFFFFFu, m1[h], off);
            int   j1 = __shfl_xor_sync(0xFFFFFFFFu, n1[h], off);
            float t2 = __shfl_xor_sync(0xFFFFFFFFu, m2[h], off);
            int   j2 = __shfl_xor_sync(0xFFFFFFFFu, n2i[h], off);
            if (t1 < m1[h]) {
                float nb2 = fminf(m1[h], t2);
                int   ni2 = (t2 < m1[h]) ? j2 : n1[h];
                m1[h] = t1; n1[h] = j1; m2[h] = nb2; n2i[h] = ni2;
            } else if (t1 < m2[h]) {
                m2[h] = t1; n2i[h] = j1;
            }
        }
    }

    // cross-N-warp merge via smem (reuse B region; all B reads done)
    float4* red = (float4*)(smem + S_B);       // [64 rows][2 wn]
    if ((l & 3) == 0) {
#pragma unroll
        for (int h = 0; h < 2; h++) {
            int row = wm * 16 + h * 8 + (l >> 2);
            red[row * 2 + wn] = make_float4(m1[h], __int_as_float(n1[h]),
                                            m2[h], __int_as_float(n2i[h]));
        }
    }
    __syncthreads();
    if (tid < MT) {
        float4 A4 = red[tid * 2 + 0];
        float4 B4 = red[tid * 2 + 1];
        float s1 = A4.x, s2 = A4.z;
        int   k1 = __float_as_int(A4.y), k2 = __float_as_int(A4.w);
        float t1 = B4.x, t2 = B4.z;
        int   j1 = __float_as_int(B4.y), j2 = __float_as_int(B4.w);
        if (t1 < s1) {
            float n2v = fminf(s1, t2);
            int   n2x = (t2 < s1) ? j2 : k1;
            s1 = t1; k1 = j1; s2 = n2v; k2 = n2x;
        } else if (t1 < s2) {
            s2 = t1; k2 = j1;
        }
        d_cand[m0 + tid] = make_int2(k1, k2);
    }
}

// ---------------------------------------------------------------------------
// finalize: exact rescore (reference-identical rounding) + gather, fused.
// ---------------------------------------------------------------------------
__global__ void __launch_bounds__(128) finalize(const float* __restrict__ ze,
                                                const float* __restrict__ cb,
                                                float* __restrict__ out) {
    __shared__ int bx[64];
    const int tid = threadIdx.x;
    const int n0  = blockIdx.x * 64;
    const int b   = n0 >> 12;
    const int hw0 = n0 & 4095;

    if (tid < 64) {
        const int n  = n0 + tid;
        const int hw = hw0 + tid;
        float x[DIM];
#pragma unroll
        for (int d = 0; d < DIM; d++)
            x[d] = ze[(size_t)(b * DIM + d) * 4096 + hw];
        float nx = 0.f;
#pragma unroll
        for (int d = 0; d < DIM; d++)
            nx = __fadd_rn(nx, __fmul_rn(x[d], x[d]));
        int2 cd = d_cand[n];
        int ka = min(cd.x, cd.y), kb = max(cd.x, cd.y);
        const float* ra = cb + (size_t)ka * DIM;
        const float* rb = cb + (size_t)kb * DIM;
        float ma = 0.f, mb = 0.f;
#pragma unroll
        for (int d = 0; d < DIM; d++) {
            ma = __fmaf_rn(x[d], ra[d], ma);
            mb = __fmaf_rn(x[d], rb[d], mb);
        }
        float d2a = __fadd_rn(__fadd_rn(nx, -__fmul_rn(2.0f, ma)), d_cn[ka]);
        float d2b = __fadd_rn(__fadd_rn(nx, -__fmul_rn(2.0f, mb)), d_cn[kb]);
        bx[tid] = (d2b < d2a) ? kb : ka;   // strict: tie -> lower index
    }
    __syncthreads();

    float* ob = out + (size_t)b * DIM * 4096 + hw0;
#pragma unroll
    for (int it = 0; it < 32; it++) {
        int e = tid + it * 128;
        int nl = e & 63, d = e >> 6;
        ob[(size_t)d * 4096 + nl] = cb[(size_t)bx[nl] * DIM + d];
    }
}

extern "C" void kernel_launch(void* const* d_in, const int* in_sizes, int n_in,
                              void* d_out, int out_size) {
    const float* ze = (const float*)d_in[0];   // [8,64,64,64] f32
    const float* cb = (const float*)d_in[1];   // [8192,64] f32
    float* out = (float*)d_out;

    cudaFuncSetAttribute(gemm_kernel, cudaFuncAttributeMaxDynamicSharedMemorySize,
                         SMEM_G);

    prep_cn<<<KC / 256, 256>>>(cb);
    prep_A<<<NP / 128, 256>>>(ze);
    prep_B<<<(KC * 100) / 256, 256>>>(cb);
    gemm_kernel<<<NP / MT, GT, SMEM_G>>>();
    finalize<<<NP / 64, 128>>>(ze, cb, out);
}